// round 12
// baseline (speedup 1.0000x reference)
#include <cuda_runtime.h>
#include <math.h>

#define SS 512
#define BB 64
#define II 256
#define HH 1024
#define BH (BB*HH)
#define NB 128          // recurrence CTAs (1/SM)
#define NT 8            // output columns per recurrence CTA
#define NTH 512         // threads per CTA (16 warps)
#define KW  64          // K-slice per warp (recurrence)
#define NWARP 16
#define NWORK 20        // xproj worker CTAs (remaining SMs)
#define NGRID (NB + NWORK)

typedef unsigned long long u64;

// packed f32x2 FMA: d = a*b + d (full fp32 precision, 2 lanes per instr)
#define FMA2(d, a, b) \
    asm("fma.rn.f32x2 %0, %1, %2, %0;" : "+l"(d) : "l"(a), "l"(b))
// pack two f32 into one u64 (for duplicated b-operands)
#define PACK2(d, lo, hi) \
    asm("mov.b64 %0, {%1, %2};" : "=l"(d) : "f"(lo), "f"(hi))

// ============================================================================
// Scratch: transposed h, double-buffered. hT[buf][k][m] (k-major, m contig).
// g_bar:    grid-barrier counters (recurrence CTAs only).
// g_xready: per-timestep xproj-completion flags (set by workers).
// Both zeroed per launch via one cudaMemsetAsync over g_sync.
// ============================================================================
__device__ __align__(16) float g_hT[2][HH * BB];
__device__ unsigned g_sync[2 * SS];   // [0..SS): barrier, [SS..2SS): xready

// ============================================================================
// Fused persistent kernel.
//  bid <  NB : recurrence CTA (all 512 steps, FFMA2 mainloop, grid barrier)
//  bid >= NB : xproj worker (timesteps t = w, w+NWORK, ... ; FFMA2 GEMM)
// Shared memory (128 KB, aliased between branches):
//  recurrence: wsf2[16384] | redA[8192] | redB[8192]   (floats)
//  worker:     xs[16384]   | ws[16384]                 (floats)
// ============================================================================
__global__ __launch_bounds__(NTH) void rnn_fused(
    const float* __restrict__ x,  const float* __restrict__ Wx,
    const float* __restrict__ bx, const float* __restrict__ Wh,
    const float* __restrict__ bh, float* __restrict__ out)
{
    extern __shared__ __align__(16) float sm[];
    const int tid = threadIdx.x;
    const int bid = blockIdx.x;

    unsigned* g_bar    = g_sync;
    unsigned* g_xready = g_sync + SS;

    // ========================================================================
    // WORKER BRANCH: xproj[t] = x_t @ Wx^T + bx  ->  out[t] (in place slab)
    // ========================================================================
    if (bid >= NB) {
        const int w = bid - NB;
        float* xs = sm;             // [256 k][64 m]  x_t transposed
        float* ws = sm + 16384;     // [256 k][64 n]  Wx chunk transposed

        const int mthr = tid & 15;          // 4 m each
        const int nthr = tid >> 4;          // 0..31, 2 n each

        for (int t = w; t < SS; t += NWORK) {
            const float* xt = x + (size_t)t * BB * II;

            // stage x_t as [k][m]
            __syncthreads();
            #pragma unroll
            for (int j = 0; j < 8; j++) {
                int idx = tid + j * NTH;        // 0..4095 float4s
                int m  = idx >> 6;
                int k4 = idx & 63;
                float4 v = *(const float4*)&xt[m * II + k4 * 4];
                xs[(k4*4+0)*64 + m] = v.x;
                xs[(k4*4+1)*64 + m] = v.y;
                xs[(k4*4+2)*64 + m] = v.z;
                xs[(k4*4+3)*64 + m] = v.w;
            }

            for (int nc = 0; nc < 16; nc++) {
                const int nC = nc * 64;
                // stage Wx chunk as [k][n]
                __syncthreads();
                #pragma unroll
                for (int j = 0; j < 8; j++) {
                    int idx = tid + j * NTH;
                    int n  = idx >> 6;
                    int k4 = idx & 63;
                    float4 v = *(const float4*)&Wx[(size_t)(nC + n) * II + k4 * 4];
                    ws[(k4*4+0)*64 + n] = v.x;
                    ws[(k4*4+1)*64 + n] = v.y;
                    ws[(k4*4+2)*64 + n] = v.z;
                    ws[(k4*4+3)*64 + n] = v.w;
                }
                __syncthreads();

                // 64m x 64n chunk: thread tile 4m x 2n, FFMA2 packed over m
                u64 acc2[2][2] = {};   // [n][m-pair]
                #pragma unroll 4
                for (int k = 0; k < II; k++) {
                    ulonglong2 a = *(const ulonglong2*)&xs[k * 64 + mthr * 4];
                    float2 b = *(const float2*)&ws[k * 64 + nthr * 2];
                    u64 b0d, b1d;
                    PACK2(b0d, b.x, b.x);
                    PACK2(b1d, b.y, b.y);
                    FMA2(acc2[0][0], a.x, b0d); FMA2(acc2[0][1], a.y, b0d);
                    FMA2(acc2[1][0], a.x, b1d); FMA2(acc2[1][1], a.y, b1d);
                }

                // epilogue: + bx, store as float2 over adjacent n
                float2 bxv = *(const float2*)&bx[nC + nthr * 2];
                #pragma unroll
                for (int p = 0; p < 2; p++) {
                    #pragma unroll
                    for (int h = 0; h < 2; h++) {
                        int m = mthr * 4 + 2 * p + h;
                        float v0 = __uint_as_float((unsigned)(h ? (acc2[0][p] >> 32)
                                                                : (acc2[0][p] & 0xFFFFFFFFu)));
                        float v1 = __uint_as_float((unsigned)(h ? (acc2[1][p] >> 32)
                                                                : (acc2[1][p] & 0xFFFFFFFFu)));
                        float2 o; o.x = v0 + bxv.x; o.y = v1 + bxv.y;
                        *(float2*)&out[(size_t)t * BH + (size_t)m * HH + nC + nthr * 2] = o;
                    }
                }
            }

            // publish timestep t
            __threadfence();
            __syncthreads();
            if (tid == 0) {
                volatile unsigned* f = &g_xready[t];
                *f = 1u;
            }
        }
        return;
    }

    // ========================================================================
    // RECURRENCE BRANCH (R11-proven + double-buffered red + flag waits)
    // ========================================================================
    float* wsf2 = sm;                        // [1024][8][2] Wh dup-pairs (64 KB)
    u64*   redA = (u64*)(sm + 16384);        // [16][256] packed partials (32 KB)
    u64*   redB = (u64*)(sm + 16384 + 8192); // second buffer (32 KB)

    const int nBase = bid * NT;
    const int ks    = tid >> 5;
    const int lane  = tid & 31;
    const int n_thr = lane & 1;
    const int m_thr = lane >> 1;
    const int k0    = ks * KW;

    // one-time Wh slice preload, duplicated pairs
    #pragma unroll
    for (int j = 0; j < 4; j++) {
        int lin = tid + j * NTH;
        int n  = lin >> 8;
        int k4 = lin & 255;
        float4 wv = *(const float4*)&Wh[(size_t)(nBase + n) * HH + k4 * 4];
        int b0 = ((k4*4+0)*8 + n)*2;  wsf2[b0]   = wv.x; wsf2[b0+1] = wv.x;
        int b1 = ((k4*4+1)*8 + n)*2;  wsf2[b1]   = wv.y; wsf2[b1+1] = wv.y;
        int b2 = ((k4*4+2)*8 + n)*2;  wsf2[b2]   = wv.z; wsf2[b2+1] = wv.z;
        int b3 = ((k4*4+3)*8 + n)*2;  wsf2[b3]   = wv.w; wsf2[b3+1] = wv.w;
    }

    const int eo_m  = tid >> 3;
    const int eo_n  = tid & 7;
    const int eo_mp = eo_m >> 1;
    const int eo_hf = eo_m & 1;
    const float bias = bh[nBase + eo_n];
    const size_t eo_idx = (size_t)eo_m * HH + nBase + eo_n;
    const int hT_idx = (nBase + eo_n) * BB + eo_m;
    const int red_off = (eo_mp * 8 + eo_n) * 2 + eo_hf;

    // wait for xproj[0], then step 0: h_0 = tanh(xproj0 + bh)
    if (tid == 0) {
        volatile unsigned* f = &g_xready[0];
        while (*f == 0u) { }
    }
    __syncthreads();
    {
        float v = tanhf(out[eo_idx] + bias);
        out[eo_idx] = v;
        g_hT[0][hT_idx] = v;
    }

    __threadfence();
    __syncthreads();
    if (tid == 0) {
        unsigned old = atomicAdd(&g_bar[0], 1u);
        if (old != NB - 1) {
            volatile unsigned* p = &g_bar[0];
            while (*p < NB) { }
        }
        volatile unsigned* f = &g_xready[1];
        while (*f == 0u) { }
    }
    __syncthreads();

    for (int t = 1; t < SS; t++) {
        const float* hT  = g_hT[(t - 1) & 1];
        float*       hTo = g_hT[t & 1];
        float*       hx  = out + (size_t)t * BH;
        u64*         red2 = (t & 1) ? redB : redA;
        const float* redf = (const float*)red2;

        float xp = __ldcg(&hx[eo_idx]);

        u64 acc2[4][2] = {};
        const float* aBase = hT + (size_t)k0 * BB + m_thr * 4;
        const float* bBase = wsf2 + (k0 * 8 + n_thr * 4) * 2;

        ulonglong2 abuf[8];
        #pragma unroll
        for (int i = 0; i < 8; i++)
            abuf[i] = __ldcg((const ulonglong2*)(aBase + i * BB));

        #pragma unroll 8
        for (int kk = 0; kk < KW - 8; kk++) {
            ulonglong2 av = abuf[kk & 7];
            abuf[kk & 7] = __ldcg((const ulonglong2*)(aBase + (kk + 8) * BB));
            ulonglong2 b01 = *(const ulonglong2*)(bBase + kk * 16);
            ulonglong2 b23 = *(const ulonglong2*)(bBase + kk * 16 + 4);
            FMA2(acc2[0][0], av.x, b01.x); FMA2(acc2[0][1], av.y, b01.x);
            FMA2(acc2[1][0], av.x, b01.y); FMA2(acc2[1][1], av.y, b01.y);
            FMA2(acc2[2][0], av.x, b23.x); FMA2(acc2[2][1], av.y, b23.x);
            FMA2(acc2[3][0], av.x, b23.y); FMA2(acc2[3][1], av.y, b23.y);
        }
        #pragma unroll
        for (int kk = KW - 8; kk < KW; kk++) {
            ulonglong2 av = abuf[kk & 7];
            ulonglong2 b01 = *(const ulonglong2*)(bBase + kk * 16);
            ulonglong2 b23 = *(const ulonglong2*)(bBase + kk * 16 + 4);
            FMA2(acc2[0][0], av.x, b01.x); FMA2(acc2[0][1], av.y, b01.x);
            FMA2(acc2[1][0], av.x, b01.y); FMA2(acc2[1][1], av.y, b01.y);
            FMA2(acc2[2][0], av.x, b23.x); FMA2(acc2[2][1], av.y, b23.x);
            FMA2(acc2[3][0], av.x, b23.y); FMA2(acc2[3][1], av.y, b23.y);
        }

        // split-K reduction (double-buffered: no pre-STS sync needed)
        #pragma unroll
        for (int p = 0; p < 2; p++) {
            int base = ks * 256 + (m_thr * 2 + p) * 8 + n_thr * 4;
            ulonglong2 v01; v01.x = acc2[0][p]; v01.y = acc2[1][p];
            ulonglong2 v23; v23.x = acc2[2][p]; v23.y = acc2[3][p];
            *(ulonglong2*)&red2[base]     = v01;
            *(ulonglong2*)&red2[base + 2] = v23;
        }
        __syncthreads();

        {
            float s = 0.f;
            #pragma unroll
            for (int p = 0; p < NWARP; p++) s += redf[p * 512 + red_off];
            float v = tanhf(s + bias + xp);
            hx[eo_idx] = v;
            hTo[hT_idx] = v;
        }

        if (t < SS - 1) {
            __threadfence();
            __syncthreads();
            if (tid == 0) {
                unsigned old = atomicAdd(&g_bar[t], 1u);
                if (old != NB - 1) {
                    volatile unsigned* p = &g_bar[t];
                    while (*p < NB) { }
                }
                volatile unsigned* f = &g_xready[t + 1];
                while (*f == 0u) { }
            }
            __syncthreads();
        }
    }
}

// ============================================================================
// Launch: one memset -> one fused kernel -> D2D h_last copy.
// ============================================================================
extern "C" void kernel_launch(void* const* d_in, const int* in_sizes, int n_in,
                              void* d_out, int out_size)
{
    const float* x  = (const float*)d_in[0];
    const float* Wx = (const float*)d_in[1];
    const float* bx = (const float*)d_in[2];
    const float* Wh = (const float*)d_in[3];
    const float* bh = (const float*)d_in[4];
    float* out = (float*)d_out;

    void* sync_ptr = nullptr;
    cudaGetSymbolAddress(&sync_ptr, g_sync);
    cudaMemsetAsync(sync_ptr, 0, 2 * SS * sizeof(unsigned));

    const int smemBytes = 32768 * sizeof(float);   // 128 KB
    cudaFuncSetAttribute(rnn_fused,
                         cudaFuncAttributeMaxDynamicSharedMemorySize, smemBytes);

    rnn_fused<<<NGRID, NTH, smemBytes>>>(x, Wx, bx, Wh, bh, out);

    cudaMemcpyAsync(out + (size_t)SS * BH, out + (size_t)(SS - 1) * BH,
                    (size_t)BH * sizeof(float), cudaMemcpyDeviceToDevice);
}

// round 13
// speedup vs baseline: 1.7179x; 1.7179x over previous
#include <cuda_runtime.h>
#include <math.h>

#define SS 512
#define BB 64
#define II 256
#define HH 1024
#define BH (BB*HH)
#define NB 128          // persistent CTAs (single wave, < 148 SMs)
#define NT 8            // output columns per CTA
#define NTH 512         // threads per CTA (16 warps)
#define KW  64          // K-slice per warp
#define NWARP 16

typedef unsigned long long u64;

// packed f32x2 FMA: d = a*b + d (full fp32 precision, 2 lanes per instr)
#define FMA2(d, a, b) \
    asm("fma.rn.f32x2 %0, %1, %2, %0;" : "+l"(d) : "l"(a), "l"(b))

// ============================================================================
// Scratch: transposed h, double-buffered. hT[buf][k][m] (k-major, m contig).
// Grid-barrier counters, zeroed per launch via cudaMemsetAsync.
// ============================================================================
__device__ __align__(16) float g_hT[2][HH * BB];
__device__ unsigned g_bar[SS];

// ============================================================================
// Kernel 1: xproj[s*B+b, h] = dot(x[s,b,:], Wx[h,:]) + bx[h]
// GEMM M=32768, K=256, N=1024. FFMA2 mainloop:
//   a: xs[kk][ty*4] LDS.128 = two {x[m],x[m+1]} pairs (m-major staging)
//   b: Wx staged as duplicated pairs {w,w} -> LDS.128 = two n-dups
// Inner iter: 3 LDS.128 + 8 FFMA2 (vs 2 LDS.128 + 16 FFMA before).
// ============================================================================
__global__ __launch_bounds__(256) void xproj_kernel(
    const float* __restrict__ x, const float* __restrict__ Wx,
    const float* __restrict__ bx, float* __restrict__ out)
{
    __shared__ __align__(16) float xs[16][68];         // [k][m]
    __shared__ __align__(16) float ws2[16][64][2];     // [k][n][dup]
    const int mBase = blockIdx.y * 64;
    const int nBase = blockIdx.x * 64;
    const int tid = threadIdx.x;
    const int tx = tid & 15;        // n-thread (4 cols each)
    const int ty = tid >> 4;        // m-thread (4 rows each = 2 m-pairs)
    const int r = tid >> 2;         // fill: row 0..63
    const int c = tid & 3;          // fill: float4 index 0..3

    u64 acc2[4][2] = {};            // [n][m-pair]

    for (int k0 = 0; k0 < II; k0 += 16) {
        float4 xa = *(const float4*)&x [(size_t)(mBase + r) * II + k0 + c * 4];
        float4 wa = *(const float4*)&Wx[(size_t)(nBase + r) * II + k0 + c * 4];
        __syncthreads();
        xs[c*4+0][r] = xa.x; xs[c*4+1][r] = xa.y; xs[c*4+2][r] = xa.z; xs[c*4+3][r] = xa.w;
        ws2[c*4+0][r][0] = wa.x; ws2[c*4+0][r][1] = wa.x;
        ws2[c*4+1][r][0] = wa.y; ws2[c*4+1][r][1] = wa.y;
        ws2[c*4+2][r][0] = wa.z; ws2[c*4+2][r][1] = wa.z;
        ws2[c*4+3][r][0] = wa.w; ws2[c*4+3][r][1] = wa.w;
        __syncthreads();
        #pragma unroll
        for (int kk = 0; kk < 16; kk++) {
            ulonglong2 av  = *(const ulonglong2*)&xs[kk][ty * 4];
            ulonglong2 b01 = *(const ulonglong2*)&ws2[kk][tx * 4][0];
            ulonglong2 b23 = *(const ulonglong2*)&ws2[kk][tx * 4 + 2][0];
            FMA2(acc2[0][0], av.x, b01.x); FMA2(acc2[0][1], av.y, b01.x);
            FMA2(acc2[1][0], av.x, b01.y); FMA2(acc2[1][1], av.y, b01.y);
            FMA2(acc2[2][0], av.x, b23.x); FMA2(acc2[2][1], av.y, b23.x);
            FMA2(acc2[3][0], av.x, b23.y); FMA2(acc2[3][1], av.y, b23.y);
        }
    }

    #pragma unroll
    for (int j = 0; j < 4; j++) {
        int col = nBase + tx * 4 + j;
        float bxv = bx[col];
        #pragma unroll
        for (int p = 0; p < 2; p++) {
            float lo = __uint_as_float((unsigned)(acc2[j][p] & 0xFFFFFFFFu));
            float hi = __uint_as_float((unsigned)(acc2[j][p] >> 32));
            int row = mBase + ty * 4 + 2 * p;
            out[(size_t)row * HH + col]       = lo + bxv;
            out[(size_t)(row + 1) * HH + col] = hi + bxv;
        }
    }
}

// ============================================================================
// Persistent RNN kernel (R11-proven, unchanged): all 512 steps.
// 16 warps x (16 m_thr x 2 n_thr), 4m x 4n per thread (m-packed FFMA2),
// K=64 per warp, LDG depth-8 pipeline, packed-u64 reduction, exact tanhf,
// atomicAdd grid barrier.
// ============================================================================
__global__ __launch_bounds__(NTH) void rnn_persistent(
    const float* __restrict__ Wh, const float* __restrict__ bh,
    float* __restrict__ out)
{
    extern __shared__ __align__(16) float sm[];
    float* wsf2 = sm;                       // [1024][8][2] Wh dup-pairs (64 KB)
    u64*   red2 = (u64*)(sm + 16384);       // [16][256]    packed partials (32 KB)

    const int tid   = threadIdx.x;
    const int nBase = blockIdx.x * NT;
    const int ks    = tid >> 5;             // warp = k-split group 0..15
    const int lane  = tid & 31;
    const int n_thr = lane & 1;             // 0..1 (4 n each)
    const int m_thr = lane >> 1;            // 0..15 (4 m each = 2 m-pairs)
    const int k0    = ks * KW;              // this warp's K range (64 wide)

    // ---- one-time Wh slice preload, duplicated: wsf2[(k*8+n)*2 + {0,1}] ----
    #pragma unroll
    for (int j = 0; j < 4; j++) {
        int lin = tid + j * NTH;            // float4 index 0..2047
        int n  = lin >> 8;                  // 0..7
        int k4 = lin & 255;                 // 0..255
        float4 w = *(const float4*)&Wh[(size_t)(nBase + n) * HH + k4 * 4];
        int b0 = ((k4*4+0)*8 + n)*2;  wsf2[b0]   = w.x; wsf2[b0+1] = w.x;
        int b1 = ((k4*4+1)*8 + n)*2;  wsf2[b1]   = w.y; wsf2[b1+1] = w.y;
        int b2 = ((k4*4+2)*8 + n)*2;  wsf2[b2]   = w.z; wsf2[b2+1] = w.z;
        int b3 = ((k4*4+3)*8 + n)*2;  wsf2[b3]   = w.w; wsf2[b3+1] = w.w;
    }

    // epilogue mapping: o = tid -> (m = o>>3, n_local = o&7)
    const int eo_m  = tid >> 3;
    const int eo_n  = tid & 7;
    const int eo_mp = eo_m >> 1;            // m-pair index
    const int eo_hf = eo_m & 1;             // which half of the pair
    const float bias = bh[nBase + eo_n];
    const size_t eo_idx = (size_t)eo_m * HH + nBase + eo_n;
    const int hT_idx = (nBase + eo_n) * BB + eo_m;
    // scalar view of packed partials for the final sum
    const float* redf = (const float*)red2;
    const int red_off = (eo_mp * 8 + eo_n) * 2 + eo_hf;

    // ---- step 0: h0 = 0  =>  h_0 = tanh(xproj0 + bh); write out + hT[0] ----
    {
        float v = tanhf(out[eo_idx] + bias);
        out[eo_idx] = v;
        g_hT[0][hT_idx] = v;
    }

    __threadfence();
    __syncthreads();
    if (tid == 0) {
        unsigned old = atomicAdd(&g_bar[0], 1u);
        if (old != NB - 1) {
            volatile unsigned* p = &g_bar[0];
            while (*p < NB) { }
        }
    }
    __syncthreads();

    // ---- steps 1..511 ----
    for (int t = 1; t < SS; t++) {
        const float* hT  = g_hT[(t - 1) & 1];
        float*       hTo = g_hT[t & 1];
        float*       hx  = out + (size_t)t * BH;

        // prefetch this thread's xproj term early (hides DRAM/L2 latency)
        float xp = __ldcg(&hx[eo_idx]);

        // acc2[n][p]: n = 0..3 (col n_thr*4+n), p = m-pair (m = m_thr*4+2p)
        u64 acc2[4][2] = {};

        const float* aBase = hT + (size_t)k0 * BB + m_thr * 4;
        const float* bBase = wsf2 + (k0 * 8 + n_thr * 4) * 2;

        // register pipeline depth 8 (covers L2 latency even at ramp)
        ulonglong2 abuf[8];
        #pragma unroll
        for (int i = 0; i < 8; i++)
            abuf[i] = __ldcg((const ulonglong2*)(aBase + i * BB));

        #pragma unroll 8
        for (int kk = 0; kk < KW - 8; kk++) {
            ulonglong2 av = abuf[kk & 7];
            abuf[kk & 7] = __ldcg((const ulonglong2*)(aBase + (kk + 8) * BB));
            ulonglong2 b01 = *(const ulonglong2*)(bBase + kk * 16);
            ulonglong2 b23 = *(const ulonglong2*)(bBase + kk * 16 + 4);
            FMA2(acc2[0][0], av.x, b01.x); FMA2(acc2[0][1], av.y, b01.x);
            FMA2(acc2[1][0], av.x, b01.y); FMA2(acc2[1][1], av.y, b01.y);
            FMA2(acc2[2][0], av.x, b23.x); FMA2(acc2[2][1], av.y, b23.x);
            FMA2(acc2[3][0], av.x, b23.y); FMA2(acc2[3][1], av.y, b23.y);
        }
        #pragma unroll
        for (int kk = KW - 8; kk < KW; kk++) {
            ulonglong2 av = abuf[kk & 7];
            ulonglong2 b01 = *(const ulonglong2*)(bBase + kk * 16);
            ulonglong2 b23 = *(const ulonglong2*)(bBase + kk * 16 + 4);
            FMA2(acc2[0][0], av.x, b01.x); FMA2(acc2[0][1], av.y, b01.x);
            FMA2(acc2[1][0], av.x, b01.y); FMA2(acc2[1][1], av.y, b01.y);
            FMA2(acc2[2][0], av.x, b23.x); FMA2(acc2[2][1], av.y, b23.x);
            FMA2(acc2[3][0], av.x, b23.y); FMA2(acc2[3][1], av.y, b23.y);
        }

        // split-K reduction: store packed pairs (2x STS.128 per thread)
        // layout: red2[ks*256 + m_pair*8 + n]  where m_pair = m_thr*2+p
        __syncthreads();
        #pragma unroll
        for (int p = 0; p < 2; p++) {
            int base = ks * 256 + (m_thr * 2 + p) * 8 + n_thr * 4;
            ulonglong2 v01; v01.x = acc2[0][p]; v01.y = acc2[1][p];
            ulonglong2 v23; v23.x = acc2[2][p]; v23.y = acc2[3][p];
            *(ulonglong2*)&red2[base]     = v01;
            *(ulonglong2*)&red2[base + 2] = v23;
        }
        __syncthreads();

        // final sum: 512 threads, one output each, scalar reads of packed red
        {
            float s = 0.f;
            #pragma unroll
            for (int p = 0; p < NWARP; p++) s += redf[p * 512 + red_off];
            float v = tanhf(s + bias + xp);
            hx[eo_idx] = v;
            hTo[hT_idx] = v;
        }

        // grid barrier between steps (none after the last step)
        if (t < SS - 1) {
            __threadfence();
            __syncthreads();
            if (tid == 0) {
                unsigned old = atomicAdd(&g_bar[t], 1u);
                if (old != NB - 1) {
                    volatile unsigned* p = &g_bar[t];
                    while (*p < NB) { }
                }
            }
            __syncthreads();
        }
    }
}

// ============================================================================
// Launch: memset barriers -> xproj -> persistent RNN -> D2D h_last copy.
// ============================================================================
extern "C" void kernel_launch(void* const* d_in, const int* in_sizes, int n_in,
                              void* d_out, int out_size)
{
    const float* x  = (const float*)d_in[0];
    const float* Wx = (const float*)d_in[1];
    const float* bx = (const float*)d_in[2];
    const float* Wh = (const float*)d_in[3];
    const float* bh = (const float*)d_in[4];
    float* out = (float*)d_out;

    void* bar_ptr = nullptr;
    cudaGetSymbolAddress(&bar_ptr, g_bar);
    cudaMemsetAsync(bar_ptr, 0, SS * sizeof(unsigned));

    const int smemBytes = 16384 * 4 + 16 * 256 * 8;   // 64 KB + 32 KB = 96 KB
    cudaFuncSetAttribute(rnn_persistent,
                         cudaFuncAttributeMaxDynamicSharedMemorySize, smemBytes);

    xproj_kernel<<<dim3(HH / 64, (SS * BB) / 64), 256>>>(x, Wx, bx, out);
    rnn_persistent<<<NB, NTH, smemBytes>>>(Wh, bh, out);

    cudaMemcpyAsync(out + (size_t)SS * BH, out + (size_t)(SS - 1) * BH,
                    (size_t)BH * sizeof(float), cudaMemcpyDeviceToDevice);
}